// round 4
// baseline (speedup 1.0000x reference)
#include <cuda_runtime.h>
#include <math.h>

#define BB   2
#define SS   2048
#define DDIM 1024
#define HH   16
#define HDIM 64
#define MM   (BB*SS)
#define NKT  32
#define CHUNK_TILES 16

typedef unsigned long long u64;

// Packed fp32x2 helpers (Blackwell FFMA2 path — ptxas never emits from C++)
__device__ __forceinline__ u64 ffma2(u64 a, u64 b, u64 c) {
    u64 d; asm("fma.rn.f32x2 %0, %1, %2, %3;" : "=l"(d) : "l"(a), "l"(b), "l"(c)); return d;
}
__device__ __forceinline__ u64 fmul2(u64 a, u64 b) {
    u64 d; asm("mul.rn.f32x2 %0, %1, %2;" : "=l"(d) : "l"(a), "l"(b)); return d;
}
__device__ __forceinline__ float lo32(u64 a){ return __uint_as_float((unsigned)a); }
__device__ __forceinline__ float hi32(u64 a){ return __uint_as_float((unsigned)(a>>32)); }
__device__ __forceinline__ u64 pack2(float l, float h){
    u64 d; asm("mov.b64 %0, {%1,%2};" : "=l"(d) : "f"(l), "f"(h)); return d;
}

// Scratch (allocation-free rule: __device__ globals)
__device__ float g_q[BB*HH*SS*HDIM];
__device__ float g_k[BB*HH*SS*HDIM];
__device__ float g_v[BB*HH*SS*HDIM];
__device__ float g_att[MM*DDIM];

// ---------------------------------------------------------------------------
// QKV projection GEMM: C = X[4096,1024] @ W[1024,1024], k-pair-packed FFMA2.
// Shared tiles hold k-interleaved pairs: As2[kk2][m] = (A[2kk2][m], A[2kk2+1][m])
// acc.lo accumulates even-k, acc.hi odd-k; summed at epilogue.
// blockIdx.z: 0=Q(+rope) 1=K(+rope) 2=V. Output layout [B,H,S,HD].
// ---------------------------------------------------------------------------
__global__ __launch_bounds__(256) void qkv_gemm_kernel(
    const float* __restrict__ X,
    const float* __restrict__ Wq,
    const float* __restrict__ Wk,
    const float* __restrict__ Wv,
    const float* __restrict__ freqs)
{
    __shared__ __align__(16) u64 As2[8*66];
    __shared__ __align__(16) u64 Bs2[8*66];
    float* Asf = (float*)As2;
    float* Bsf = (float*)Bs2;

    const int mode = blockIdx.z;
    const float* __restrict__ W = (mode == 0) ? Wq : (mode == 1) ? Wk : Wv;
    const int m0 = blockIdx.y * 64;
    const int n0 = blockIdx.x * 64;
    const int t  = threadIdx.x;
    const int tx = t & 15, ty = t >> 4;
    const int tx4 = tx*4, ty4 = ty*4;
    const int ar = t >> 2, ak = (t & 3) * 4;     // A: row 0..63, k 0,4,8,12
    const int kp = t >> 5, ns = (t & 31) * 2;    // B: k-pair 0..7, n 0..62

    u64 acc2[4][4] = {};

    for (int k0 = 0; k0 < DDIM; k0 += 16) {
        float4 av = *(const float4*)&X[(m0 + ar) * DDIM + k0 + ak];
        float2 b0 = *(const float2*)&W[(k0 + 2*kp    ) * DDIM + n0 + ns];
        float2 b1 = *(const float2*)&W[(k0 + 2*kp + 1) * DDIM + n0 + ns];
        __syncthreads();
        *(float2*)&Asf[(((ak>>1)  )*66 + ar)*2] = make_float2(av.x, av.y);
        *(float2*)&Asf[(((ak>>1)+1)*66 + ar)*2] = make_float2(av.z, av.w);
        *(float2*)&Bsf[(kp*66 + ns  )*2] = make_float2(b0.x, b1.x);
        *(float2*)&Bsf[(kp*66 + ns+1)*2] = make_float2(b0.y, b1.y);
        __syncthreads();
        #pragma unroll
        for (int kk = 0; kk < 8; kk++) {
            ulonglong2 a01 = *(const ulonglong2*)&As2[kk*66 + ty4];
            ulonglong2 a23 = *(const ulonglong2*)&As2[kk*66 + ty4 + 2];
            ulonglong2 b01 = *(const ulonglong2*)&Bs2[kk*66 + tx4];
            ulonglong2 b23 = *(const ulonglong2*)&Bs2[kk*66 + tx4 + 2];
            u64 aa[4] = {a01.x, a01.y, a23.x, a23.y};
            u64 bb[4] = {b01.x, b01.y, b23.x, b23.y};
            #pragma unroll
            for (int i = 0; i < 4; i++)
                #pragma unroll
                for (int j = 0; j < 4; j++)
                    acc2[i][j] = ffma2(aa[i], bb[j], acc2[i][j]);
        }
    }

    float acc[4][4];
    #pragma unroll
    for (int i = 0; i < 4; i++)
        #pragma unroll
        for (int j = 0; j < 4; j++)
            acc[i][j] = lo32(acc2[i][j]) + hi32(acc2[i][j]);

    const int hh = n0 >> 6;
    const int nl = tx * 4;
    if (mode == 2) {
        float* __restrict__ dst = g_v;
        #pragma unroll
        for (int i = 0; i < 4; i++) {
            int m = m0 + ty4 + i;
            int b = m >> 11, s = m & 2047;
            float4 r = make_float4(acc[i][0], acc[i][1], acc[i][2], acc[i][3]);
            *(float4*)&dst[((b*HH + hh)*SS + s)*HDIM + nl] = r;
        }
    } else {
        float* __restrict__ dst = (mode == 0) ? g_q : g_k;
        #pragma unroll
        for (int i = 0; i < 4; i++) {
            int m = m0 + ty4 + i;
            int b = m >> 11, s = m & 2047;
            const float* F = freqs + s*HDIM + nl;
            float c0 = F[0], s0 = F[1], c1 = F[2], s1 = F[3];
            float a0 = acc[i][0], b0 = acc[i][1];
            float a1 = acc[i][2], b1 = acc[i][3];
            float4 r;
            r.x = a0*c0 - b0*s0;
            r.y = a0*s0 + b0*c0;
            r.z = a1*c1 - b1*s1;
            r.w = a1*s1 + b1*c1;
            *(float4*)&dst[((b*HH + hh)*SS + s)*HDIM + nl] = r;
        }
    }
}

// ---------------------------------------------------------------------------
// Attention, FFMA2 everywhere. Pack along d for QK^T, along k for PV.
// Per-1024-key chunk softmax normalization + reset (replicates reference bug).
// Shared (u64 slots):
//   Qs2[d2][q]  32x(66)   (Q[2d2][q], Q[2d2+1][q])
//   Ks2[d2][k]  32x(66)
//   Vs2[k2][d]  32x(66)   (V[2k2][d], V[2k2+1][d])
//   Ps2[q][k2]  64x(34)   (P[q][2k2], P[q][2k2+1])  == old row-major layout
// ---------------------------------------------------------------------------
#define ATT_SMEM ((3*32*66 + 64*34) * 8)

__global__ __launch_bounds__(256) void attn_kernel()
{
    extern __shared__ __align__(16) u64 sm2[];
    u64* Qs2 = sm2;
    u64* Ks2 = sm2 + 32*66;
    u64* Vs2 = sm2 + 2*32*66;
    u64* Ps2 = sm2 + 3*32*66;
    float* Qsf = (float*)Qs2;
    float* Ksf = (float*)Ks2;
    float* Vsf = (float*)Vs2;
    float* Psf = (float*)Ps2;

    const int qt = blockIdx.x;
    const int h  = blockIdx.y;
    const int b  = blockIdx.z;
    const int t  = threadIdx.x;
    const int tx = t & 15, ty = t >> 4;
    const int tx4 = tx * 4, ty4 = ty * 4;
    const int dd = tx4;

    const float* __restrict__ Qg = g_q + (((size_t)b*HH + h)*SS + qt*64) * HDIM;
    const float* __restrict__ Kg = g_k + (((size_t)b*HH + h)*SS) * HDIM;
    const float* __restrict__ Vg = g_v + (((size_t)b*HH + h)*SS) * HDIM;

    // Load Q tile, d-pair interleaved
    #pragma unroll
    for (int r = 0; r < 4; r++) {
        int row = (t >> 4) + r * 16;
        float4 v = *(const float4*)&Qg[row*HDIM + dd];
        *(float2*)&Qsf[(((dd>>1)  )*66 + row)*2] = make_float2(v.x, v.y);
        *(float2*)&Qsf[(((dd>>1)+1)*66 + row)*2] = make_float2(v.z, v.w);
    }

    float m[4], l[4], oT[4][4] = {};
    u64 o2[4][4] = {};
    #pragma unroll
    for (int i = 0; i < 4; i++) { m[i] = -INFINITY; l[i] = 0.f; }

    for (int kt = 0; kt < NKT; kt++) {
        __syncthreads();   // protect previous iteration's Vs/Ps reads
        // K: d-pair interleaved; V: k-pair interleaved
        #pragma unroll
        for (int r = 0; r < 4; r++) {
            int row = (t >> 4) + r * 16;
            float4 kv = *(const float4*)&Kg[(kt*64 + row)*HDIM + dd];
            *(float2*)&Ksf[(((dd>>1)  )*66 + row)*2] = make_float2(kv.x, kv.y);
            *(float2*)&Ksf[(((dd>>1)+1)*66 + row)*2] = make_float2(kv.z, kv.w);
        }
        #pragma unroll
        for (int r = 0; r < 2; r++) {
            int k2 = (t >> 4) + r * 16;
            float4 v0 = *(const float4*)&Vg[(kt*64 + 2*k2    )*HDIM + dd];
            float4 v1 = *(const float4*)&Vg[(kt*64 + 2*k2 + 1)*HDIM + dd];
            *(float2*)&Vsf[(k2*66 + dd+0)*2] = make_float2(v0.x, v1.x);
            *(float2*)&Vsf[(k2*66 + dd+1)*2] = make_float2(v0.y, v1.y);
            *(float2*)&Vsf[(k2*66 + dd+2)*2] = make_float2(v0.z, v1.z);
            *(float2*)&Vsf[(k2*66 + dd+3)*2] = make_float2(v0.w, v1.w);
        }
        __syncthreads();

        // S = Q @ K^T : 64x64x64, packed along d
        u64 s2[4][4] = {};
        #pragma unroll 8
        for (int d2 = 0; d2 < 32; d2++) {
            ulonglong2 qa = *(const ulonglong2*)&Qs2[d2*66 + ty4];
            ulonglong2 qb = *(const ulonglong2*)&Qs2[d2*66 + ty4 + 2];
            ulonglong2 ka = *(const ulonglong2*)&Ks2[d2*66 + tx4];
            ulonglong2 kb = *(const ulonglong2*)&Ks2[d2*66 + tx4 + 2];
            u64 aa[4] = {qa.x, qa.y, qb.x, qb.y};
            u64 bb[4] = {ka.x, ka.y, kb.x, kb.y};
            #pragma unroll
            for (int i = 0; i < 4; i++)
                #pragma unroll
                for (int j = 0; j < 4; j++)
                    s2[i][j] = ffma2(aa[i], bb[j], s2[i][j]);
        }

        // Online softmax, reduce across 16 tx lanes
        #pragma unroll
        for (int i = 0; i < 4; i++) {
            float s[4];
            float mt = -INFINITY;
            #pragma unroll
            for (int j = 0; j < 4; j++) {
                s[j] = (lo32(s2[i][j]) + hi32(s2[i][j])) * 0.125f;
                mt = fmaxf(mt, s[j]);
            }
            #pragma unroll
            for (int ofs = 8; ofs >= 1; ofs >>= 1)
                mt = fmaxf(mt, __shfl_xor_sync(0xffffffffu, mt, ofs));
            float mn = fmaxf(m[i], mt);
            float alpha = __expf(m[i] - mn);
            float rs = 0.f;
            #pragma unroll
            for (int j = 0; j < 4; j++) {
                s[j] = __expf(s[j] - mn);
                rs += s[j];
            }
            #pragma unroll
            for (int ofs = 8; ofs >= 1; ofs >>= 1)
                rs += __shfl_xor_sync(0xffffffffu, rs, ofs);
            l[i] = l[i] * alpha + rs;
            m[i] = mn;
            u64 al2 = pack2(alpha, alpha);
            #pragma unroll
            for (int j = 0; j < 4; j++) o2[i][j] = fmul2(o2[i][j], al2);
            // stage P row (row-major == k-pair packed)
            *(float4*)&Psf[(ty4+i)*68 + tx4] = make_float4(s[0], s[1], s[2], s[3]);
        }
        __syncthreads();

        // O += P @ V : packed along k
        #pragma unroll 4
        for (int k2 = 0; k2 < 32; k2 += 2) {
            ulonglong2 p0 = *(const ulonglong2*)&Ps2[(ty4+0)*34 + k2];
            ulonglong2 p1 = *(const ulonglong2*)&Ps2[(ty4+1)*34 + k2];
            ulonglong2 p2v = *(const ulonglong2*)&Ps2[(ty4+2)*34 + k2];
            ulonglong2 p3 = *(const ulonglong2*)&Ps2[(ty4+3)*34 + k2];
            ulonglong2 va = *(const ulonglong2*)&Vs2[k2*66 + tx4];
            ulonglong2 vb = *(const ulonglong2*)&Vs2[k2*66 + tx4 + 2];
            ulonglong2 vc = *(const ulonglong2*)&Vs2[(k2+1)*66 + tx4];
            ulonglong2 vd = *(const ulonglong2*)&Vs2[(k2+1)*66 + tx4 + 2];
            u64 pA[4] = {p0.x, p1.x, p2v.x, p3.x};   // k-pair k2
            u64 pB[4] = {p0.y, p1.y, p2v.y, p3.y};   // k-pair k2+1
            u64 vA[4] = {va.x, va.y, vb.x, vb.y};
            u64 vB[4] = {vc.x, vc.y, vd.x, vd.y};
            #pragma unroll
            for (int i = 0; i < 4; i++)
                #pragma unroll
                for (int j = 0; j < 4; j++) {
                    o2[i][j] = ffma2(pA[i], vA[j], o2[i][j]);
                    o2[i][j] = ffma2(pB[i], vB[j], o2[i][j]);
                }
        }

        // Chunk boundary: normalize by chunk softmax sum, accumulate, reset
        if ((kt & (CHUNK_TILES - 1)) == (CHUNK_TILES - 1)) {
            #pragma unroll
            for (int i = 0; i < 4; i++) {
                float inv = 1.f / l[i];
                #pragma unroll
                for (int j = 0; j < 4; j++) {
                    oT[i][j] += (lo32(o2[i][j]) + hi32(o2[i][j])) * inv;
                    o2[i][j] = 0ull;
                }
                m[i] = -INFINITY;
                l[i] = 0.f;
            }
        }
    }

    // Store to [B,S,D]
    #pragma unroll
    for (int i = 0; i < 4; i++) {
        int q = qt*64 + ty4 + i;
        float4 r = make_float4(oT[i][0], oT[i][1], oT[i][2], oT[i][3]);
        *(float4*)&g_att[((size_t)(b*SS + q))*DDIM + h*HDIM + tx4] = r;
    }
}

// ---------------------------------------------------------------------------
// Output projection: d_out = g_att[4096,1024] @ Wo[1024,1024], FFMA2 packed.
// ---------------------------------------------------------------------------
__global__ __launch_bounds__(256) void out_gemm_kernel(
    const float* __restrict__ Wo, float* __restrict__ out)
{
    __shared__ __align__(16) u64 As2[8*66];
    __shared__ __align__(16) u64 Bs2[8*66];
    float* Asf = (float*)As2;
    float* Bsf = (float*)Bs2;

    const int m0 = blockIdx.y * 64;
    const int n0 = blockIdx.x * 64;
    const int t  = threadIdx.x;
    const int tx = t & 15, ty = t >> 4;
    const int tx4 = tx*4, ty4 = ty*4;
    const int ar = t >> 2, ak = (t & 3) * 4;
    const int kp = t >> 5, ns = (t & 31) * 2;

    u64 acc2[4][4] = {};

    for (int k0 = 0; k0 < DDIM; k0 += 16) {
        float4 av = *(const float4*)&g_att[(size_t)(m0 + ar) * DDIM + k0 + ak];
        float2 b0 = *(const float2*)&Wo[(k0 + 2*kp    ) * DDIM + n0 + ns];
        float2 b1 = *(const float2*)&Wo[(k0 + 2*kp + 1) * DDIM + n0 + ns];
        __syncthreads();
        *(float2*)&Asf[(((ak>>1)  )*66 + ar)*2] = make_float2(av.x, av.y);
        *(float2*)&Asf[(((ak>>1)+1)*66 + ar)*2] = make_float2(av.z, av.w);
        *(float2*)&Bsf[(kp*66 + ns  )*2] = make_float2(b0.x, b1.x);
        *(float2*)&Bsf[(kp*66 + ns+1)*2] = make_float2(b0.y, b1.y);
        __syncthreads();
        #pragma unroll
        for (int kk = 0; kk < 8; kk++) {
            ulonglong2 a01 = *(const ulonglong2*)&As2[kk*66 + ty4];
            ulonglong2 a23 = *(const ulonglong2*)&As2[kk*66 + ty4 + 2];
            ulonglong2 b01 = *(const ulonglong2*)&Bs2[kk*66 + tx4];
            ulonglong2 b23 = *(const ulonglong2*)&Bs2[kk*66 + tx4 + 2];
            u64 aa[4] = {a01.x, a01.y, a23.x, a23.y};
            u64 bb[4] = {b01.x, b01.y, b23.x, b23.y};
            #pragma unroll
            for (int i = 0; i < 4; i++)
                #pragma unroll
                for (int j = 0; j < 4; j++)
                    acc2[i][j] = ffma2(aa[i], bb[j], acc2[i][j]);
        }
    }

    #pragma unroll
    for (int i = 0; i < 4; i++) {
        int mrow = m0 + ty4 + i;
        float4 r;
        r.x = lo32(acc2[i][0]) + hi32(acc2[i][0]);
        r.y = lo32(acc2[i][1]) + hi32(acc2[i][1]);
        r.z = lo32(acc2[i][2]) + hi32(acc2[i][2]);
        r.w = lo32(acc2[i][3]) + hi32(acc2[i][3]);
        *(float4*)&out[(size_t)mrow * DDIM + n0 + tx4] = r;
    }
}

// ---------------------------------------------------------------------------
extern "C" void kernel_launch(void* const* d_in, const int* in_sizes, int n_in,
                              void* d_out, int out_size)
{
    const float* X     = (const float*)d_in[0];
    const float* freqs = (const float*)d_in[1];
    const float* Wq    = (const float*)d_in[2];
    const float* Wk    = (const float*)d_in[3];
    const float* Wv    = (const float*)d_in[4];
    const float* Wo    = (const float*)d_in[5];
    float* out = (float*)d_out;

    cudaFuncSetAttribute(attn_kernel,
                         cudaFuncAttributeMaxDynamicSharedMemorySize, ATT_SMEM);

    qkv_gemm_kernel<<<dim3(16, 64, 3), 256>>>(X, Wq, Wk, Wv, freqs);
    attn_kernel<<<dim3(32, HH, BB), 256, ATT_SMEM>>>();
    out_gemm_kernel<<<dim3(16, 64, 1), 256>>>(Wo, out);
}

// round 5
// speedup vs baseline: 3.2007x; 3.2007x over previous
#include <cuda_runtime.h>
#include <cuda_bf16.h>
#include <math.h>

#define BB 2
#define SS 2048
#define DDIM 1024
#define HH 16
#define HDIM 64
#define MM (BB*SS)
#define NKT 32

typedef unsigned int u32;
typedef unsigned short u16;
typedef __nv_bfloat16 bf16;

// ---- scratch (allocation-free rule: __device__ globals) ----
__device__ __align__(16) bf16 g_xhi[MM*DDIM], g_xlo[MM*DDIM];
__device__ __align__(16) bf16 g_whi[4][DDIM*DDIM], g_wlo[4][DDIM*DDIM];   // Wq,Wk,Wv,Wo
__device__ __align__(16) bf16 g_qhi[MM*DDIM], g_qlo[MM*DDIM];             // [B,H,S,HD]
__device__ __align__(16) bf16 g_khi[MM*DDIM], g_klo[MM*DDIM];
__device__ __align__(16) bf16 g_vhi[MM*DDIM], g_vlo[MM*DDIM];
__device__ __align__(16) bf16 g_ahi[MM*DDIM], g_alo[MM*DDIM];             // attn out [B,S,D]

// ---- helpers ----
__device__ __forceinline__ u32 sptr(const void* p){ return (u32)__cvta_generic_to_shared(p); }

__device__ __forceinline__ void ldsm4(u32& r0,u32& r1,u32& r2,u32& r3,u32 a){
    asm volatile("ldmatrix.sync.aligned.m8n8.x4.shared.b16 {%0,%1,%2,%3}, [%4];"
                 : "=r"(r0),"=r"(r1),"=r"(r2),"=r"(r3) : "r"(a));
}
__device__ __forceinline__ void ldsm2(u32& r0,u32& r1,u32 a){
    asm volatile("ldmatrix.sync.aligned.m8n8.x2.shared.b16 {%0,%1}, [%2];"
                 : "=r"(r0),"=r"(r1) : "r"(a));
}
__device__ __forceinline__ void ldsm2t(u32& r0,u32& r1,u32 a){
    asm volatile("ldmatrix.sync.aligned.m8n8.x2.trans.shared.b16 {%0,%1}, [%2];"
                 : "=r"(r0),"=r"(r1) : "r"(a));
}
__device__ __forceinline__ void mma16816(float* c, const u32* a, const u32* b){
    asm volatile("mma.sync.aligned.m16n8k16.row.col.f32.bf16.bf16.f32 "
                 "{%0,%1,%2,%3},{%4,%5,%6,%7},{%8,%9},{%0,%1,%2,%3};"
                 : "+f"(c[0]),"+f"(c[1]),"+f"(c[2]),"+f"(c[3])
                 : "r"(a[0]),"r"(a[1]),"r"(a[2]),"r"(a[3]),"r"(b[0]),"r"(b[1]));
}
__device__ __forceinline__ u16 us(bf16 x){ return __bfloat16_as_ushort(x); }
// split fp32 -> (hi, lo) bf16
__device__ __forceinline__ void split1(float x, bf16& h, bf16& l){
    h = __float2bfloat16(x);
    l = __float2bfloat16(x - __bfloat162float(h));
}

// ---------------------------------------------------------------------------
// Prep: split fp32 tensor into bf16 hi/lo. which: 0=X, 1..4=Wq,Wk,Wv,Wo
// ---------------------------------------------------------------------------
__global__ __launch_bounds__(256) void split_kernel(const float* __restrict__ src,
                                                    int which, int n4)
{
    int i = blockIdx.x * blockDim.x + threadIdx.x;
    if (i >= n4) return;
    bf16 *hi, *lo;
    if (which == 0) { hi = g_xhi; lo = g_xlo; }
    else            { hi = g_whi[which-1]; lo = g_wlo[which-1]; }
    float4 v = ((const float4*)src)[i];
    bf16 h0,l0,h1,l1,h2,l2,h3,l3;
    split1(v.x,h0,l0); split1(v.y,h1,l1); split1(v.z,h2,l2); split1(v.w,h3,l3);
    uint2 hw, lw;
    hw.x = (u32)us(h0) | ((u32)us(h1) << 16);
    hw.y = (u32)us(h2) | ((u32)us(h3) << 16);
    lw.x = (u32)us(l0) | ((u32)us(l1) << 16);
    lw.y = (u32)us(l2) | ((u32)us(l3) << 16);
    *(uint2*)&hi[i*4] = hw;
    *(uint2*)&lo[i*4] = lw;
}

// ---------------------------------------------------------------------------
// QKV projection: C = X @ W, bf16 hi/lo split MMA (3 mmas), rope epilogue.
// Block 256 thr (8 warps, 4m x 2n), tile 128x128, k-step 32.
// blockIdx.z: 0=Q(+rope) 1=K(+rope) 2=V. Output bf16 hi/lo [B,H,S,HD].
// ---------------------------------------------------------------------------
__global__ __launch_bounds__(256) void qkv_mma_kernel(const float* __restrict__ freqs)
{
    __shared__ __align__(16) bf16 Ahi[128*40], Alo[128*40];
    __shared__ __align__(16) bf16 Bhi[32*136], Blo[32*136];

    const int mode = blockIdx.z;
    const bf16* __restrict__ Whi = g_whi[mode];
    const bf16* __restrict__ Wlo = g_wlo[mode];
    const int m0 = blockIdx.y * 128;
    const int n0 = blockIdx.x * 128;
    const int t = threadIdx.x, lane = t & 31, w = t >> 5;
    const int wm = w & 3, wn = w >> 2;

    const int arow = t >> 1, acol = (t & 1) * 16;
    const int brow = t >> 3, bcol = (t & 7) * 16;

    float acc[2][8][4] = {};

    for (int k0 = 0; k0 < DDIM; k0 += 32) {
        uint4 a0h = *(const uint4*)&g_xhi[(m0+arow)*DDIM + k0 + acol];
        uint4 a1h = *(const uint4*)&g_xhi[(m0+arow)*DDIM + k0 + acol + 8];
        uint4 a0l = *(const uint4*)&g_xlo[(m0+arow)*DDIM + k0 + acol];
        uint4 a1l = *(const uint4*)&g_xlo[(m0+arow)*DDIM + k0 + acol + 8];
        uint4 b0h = *(const uint4*)&Whi[(k0+brow)*DDIM + n0 + bcol];
        uint4 b1h = *(const uint4*)&Whi[(k0+brow)*DDIM + n0 + bcol + 8];
        uint4 b0l = *(const uint4*)&Wlo[(k0+brow)*DDIM + n0 + bcol];
        uint4 b1l = *(const uint4*)&Wlo[(k0+brow)*DDIM + n0 + bcol + 8];
        __syncthreads();
        *(uint4*)&Ahi[arow*40 + acol]     = a0h;
        *(uint4*)&Ahi[arow*40 + acol + 8] = a1h;
        *(uint4*)&Alo[arow*40 + acol]     = a0l;
        *(uint4*)&Alo[arow*40 + acol + 8] = a1l;
        *(uint4*)&Bhi[brow*136 + bcol]     = b0h;
        *(uint4*)&Bhi[brow*136 + bcol + 8] = b1h;
        *(uint4*)&Blo[brow*136 + bcol]     = b0l;
        *(uint4*)&Blo[brow*136 + bcol + 8] = b1l;
        __syncthreads();

        #pragma unroll
        for (int kk = 0; kk < 2; kk++) {
            u32 afh[2][4], afl[2][4];
            #pragma unroll
            for (int mi = 0; mi < 2; mi++) {
                int r = wm*32 + mi*16 + (lane & 15);
                int c = kk*16 + ((lane >> 4) & 1) * 8;
                ldsm4(afh[mi][0],afh[mi][1],afh[mi][2],afh[mi][3], sptr(&Ahi[r*40 + c]));
                ldsm4(afl[mi][0],afl[mi][1],afl[mi][2],afl[mi][3], sptr(&Alo[r*40 + c]));
            }
            #pragma unroll
            for (int nj = 0; nj < 8; nj++) {
                u32 bh[2], bl[2];
                int r = kk*16 + (lane & 15);
                int c = wn*64 + nj*8;
                ldsm2t(bh[0], bh[1], sptr(&Bhi[r*136 + c]));
                ldsm2t(bl[0], bl[1], sptr(&Blo[r*136 + c]));
                #pragma unroll
                for (int mi = 0; mi < 2; mi++) {
                    mma16816(acc[mi][nj], afh[mi], bh);
                    mma16816(acc[mi][nj], afh[mi], bl);
                    mma16816(acc[mi][nj], afl[mi], bh);
                }
            }
        }
    }

    // epilogue: rope (Q,K) or plain (V), split to bf16 hi/lo, store [B,H,S,HD]
    bf16* __restrict__ dh = (mode == 0) ? g_qhi : (mode == 1) ? g_khi : g_vhi;
    bf16* __restrict__ dl = (mode == 0) ? g_qlo : (mode == 1) ? g_klo : g_vlo;
    #pragma unroll
    for (int mi = 0; mi < 2; mi++) {
        int ra = m0 + wm*32 + mi*16 + (lane >> 2);
        #pragma unroll
        for (int nj = 0; nj < 8; nj++) {
            int col = n0 + wn*64 + nj*8 + (lane & 3)*2;
            int hh = col >> 6, dd = col & 63;
            #pragma unroll
            for (int half = 0; half < 2; half++) {
                int r = ra + half*8;
                int b = r >> 11, s = r & 2047;
                float x = acc[mi][nj][half*2], y = acc[mi][nj][half*2+1];
                if (mode < 2) {
                    float cs = freqs[s*HDIM + dd], sn = freqs[s*HDIM + dd + 1];
                    float nx = x*cs - y*sn;
                    float ny = x*sn + y*cs;
                    x = nx; y = ny;
                }
                bf16 xh,xl,yh,yl;
                split1(x,xh,xl); split1(y,yh,yl);
                size_t idx = ((size_t)(b*HH + hh)*SS + s)*HDIM + dd;
                *(u32*)&dh[idx] = (u32)us(xh) | ((u32)us(yh) << 16);
                *(u32*)&dl[idx] = (u32)us(xl) | ((u32)us(yl) << 16);
            }
        }
    }
}

// ---------------------------------------------------------------------------
// Attention: block = 128 thr (4 warps), 64 q rows (warp -> m16), HD=64.
// S = Q K^T via 3-mma split; online per-1024-key-chunk softmax (replicates
// reference's chunked normalization bug); P repacked reg->reg as A fragment;
// O += P V via 3-mma split. Output bf16 hi/lo [B,S,D].
// ---------------------------------------------------------------------------
#define ASMEM (6 * 64 * 72 * 2)

__global__ __launch_bounds__(128) void attn_mma_kernel()
{
    extern __shared__ __align__(16) bf16 sm[];
    bf16* Qh = sm;
    bf16* Ql = Qh + 64*72;
    bf16* Kh = Ql + 64*72;
    bf16* Kl = Kh + 64*72;
    bf16* Vh = Kl + 64*72;
    bf16* Vl = Vh + 64*72;

    const int qt = blockIdx.x, h = blockIdx.y, b = blockIdx.z;
    const int t = threadIdx.x, lane = t & 31, w = t >> 5;

    const size_t base = ((size_t)(b*HH + h))*SS*HDIM;
    const bf16* __restrict__ Qgh = g_qhi + base + (size_t)qt*64*HDIM;
    const bf16* __restrict__ Qgl = g_qlo + base + (size_t)qt*64*HDIM;
    const bf16* __restrict__ Kgh = g_khi + base;
    const bf16* __restrict__ Kgl = g_klo + base;
    const bf16* __restrict__ Vgh = g_vhi + base;
    const bf16* __restrict__ Vgl = g_vlo + base;

    // Load Q tile (64x64) hi/lo
    {
        int row = t >> 1, c = (t & 1) * 32;
        #pragma unroll
        for (int i = 0; i < 4; i++) {
            *(uint4*)&Qh[row*72 + c + i*8] = *(const uint4*)&Qgh[row*64 + c + i*8];
            *(uint4*)&Ql[row*72 + c + i*8] = *(const uint4*)&Qgl[row*64 + c + i*8];
        }
    }
    __syncthreads();

    // Resident Q fragments (4 k16 groups)
    u32 qfh[4][4], qfl[4][4];
    #pragma unroll
    for (int g = 0; g < 4; g++) {
        int r = w*16 + (lane & 15);
        int c = g*16 + ((lane >> 4) & 1) * 8;
        ldsm4(qfh[g][0],qfh[g][1],qfh[g][2],qfh[g][3], sptr(&Qh[r*72 + c]));
        ldsm4(qfl[g][0],qfl[g][1],qfl[g][2],qfl[g][3], sptr(&Ql[r*72 + c]));
    }

    float o[8][4] = {}, oT[8][4] = {};
    float mA = -INFINITY, lA = 0.f, mB = -INFINITY, lB = 0.f;

    for (int kt = 0; kt < NKT; kt++) {
        __syncthreads();
        {
            int row = t >> 1, c = (t & 1) * 32;
            const bf16* kh = Kgh + (size_t)(kt*64 + row)*64;
            const bf16* kl = Kgl + (size_t)(kt*64 + row)*64;
            const bf16* vh = Vgh + (size_t)(kt*64 + row)*64;
            const bf16* vl = Vgl + (size_t)(kt*64 + row)*64;
            #pragma unroll
            for (int i = 0; i < 4; i++) {
                *(uint4*)&Kh[row*72 + c + i*8] = *(const uint4*)&kh[c + i*8];
                *(uint4*)&Kl[row*72 + c + i*8] = *(const uint4*)&kl[c + i*8];
                *(uint4*)&Vh[row*72 + c + i*8] = *(const uint4*)&vh[c + i*8];
                *(uint4*)&Vl[row*72 + c + i*8] = *(const uint4*)&vl[c + i*8];
            }
        }
        __syncthreads();

        // S = Q @ K^T : m16 x n64 x k64
        float s[8][4] = {};
        #pragma unroll
        for (int g = 0; g < 4; g++) {
            #pragma unroll
            for (int nj = 0; nj < 8; nj++) {
                u32 kh2[2], kl2[2];
                int r = nj*8 + (lane & 7);
                int c = g*16 + ((lane >> 3) & 1) * 8;
                ldsm2(kh2[0], kh2[1], sptr(&Kh[r*72 + c]));
                ldsm2(kl2[0], kl2[1], sptr(&Kl[r*72 + c]));
                mma16816(s[nj], qfh[g], kh2);
                mma16816(s[nj], qfh[g], kl2);
                mma16816(s[nj], qfl[g], kh2);
            }
        }

        // online softmax (rows ra = l/4, rb = ra+8), quad reduce (xor 1,2)
        float mtA = -INFINITY, mtB = -INFINITY;
        #pragma unroll
        for (int nj = 0; nj < 8; nj++) {
            #pragma unroll
            for (int q4 = 0; q4 < 4; q4++) s[nj][q4] *= 0.125f;
            mtA = fmaxf(mtA, fmaxf(s[nj][0], s[nj][1]));
            mtB = fmaxf(mtB, fmaxf(s[nj][2], s[nj][3]));
        }
        #pragma unroll
        for (int ofs = 1; ofs <= 2; ofs <<= 1) {
            mtA = fmaxf(mtA, __shfl_xor_sync(0xffffffffu, mtA, ofs));
            mtB = fmaxf(mtB, __shfl_xor_sync(0xffffffffu, mtB, ofs));
        }
        float mnA = fmaxf(mA, mtA), mnB = fmaxf(mB, mtB);
        float alA = __expf(mA - mnA), alB = __expf(mB - mnB);
        float rsA = 0.f, rsB = 0.f;
        #pragma unroll
        for (int nj = 0; nj < 8; nj++) {
            s[nj][0] = __expf(s[nj][0] - mnA);
            s[nj][1] = __expf(s[nj][1] - mnA);
            s[nj][2] = __expf(s[nj][2] - mnB);
            s[nj][3] = __expf(s[nj][3] - mnB);
            rsA += s[nj][0] + s[nj][1];
            rsB += s[nj][2] + s[nj][3];
        }
        #pragma unroll
        for (int ofs = 1; ofs <= 2; ofs <<= 1) {
            rsA += __shfl_xor_sync(0xffffffffu, rsA, ofs);
            rsB += __shfl_xor_sync(0xffffffffu, rsB, ofs);
        }
        lA = lA * alA + rsA;  mA = mnA;
        lB = lB * alB + rsB;  mB = mnB;
        #pragma unroll
        for (int nj = 0; nj < 8; nj++) {
            o[nj][0] *= alA; o[nj][1] *= alA;
            o[nj][2] *= alB; o[nj][3] *= alB;
        }

        // repack P (C-frag) -> A-frag, hi/lo split, registers only
        u32 pfh[4][4], pfl[4][4];
        #pragma unroll
        for (int g = 0; g < 4; g++) {
            #pragma unroll
            for (int q4 = 0; q4 < 4; q4++) {
                int tile = 2*g + (q4 >> 1);
                float p0 = s[tile][(q4 & 1)*2], p1 = s[tile][(q4 & 1)*2 + 1];
                bf16 h0,l0,h1,l1;
                split1(p0,h0,l0); split1(p1,h1,l1);
                pfh[g][q4] = (u32)us(h0) | ((u32)us(h1) << 16);
                pfl[g][q4] = (u32)us(l0) | ((u32)us(l1) << 16);
            }
        }

        // O += P @ V : m16 x n64 x k64
        #pragma unroll
        for (int g = 0; g < 4; g++) {
            #pragma unroll
            for (int nj = 0; nj < 8; nj++) {
                u32 vh2[2], vl2[2];
                int r = g*16 + (lane & 15);
                ldsm2t(vh2[0], vh2[1], sptr(&Vh[r*72 + nj*8]));
                ldsm2t(vl2[0], vl2[1], sptr(&Vl[r*72 + nj*8]));
                mma16816(o[nj], pfh[g], vh2);
                mma16816(o[nj], pfh[g], vl2);
                mma16816(o[nj], pfl[g], vh2);
            }
        }

        // chunk boundary (1024 keys = 16 tiles): normalize, accumulate, reset
        if ((kt & 15) == 15) {
            float iA = 1.f / lA, iB = 1.f / lB;
            #pragma unroll
            for (int nj = 0; nj < 8; nj++) {
                oT[nj][0] += o[nj][0] * iA;  oT[nj][1] += o[nj][1] * iA;
                oT[nj][2] += o[nj][2] * iB;  oT[nj][3] += o[nj][3] * iB;
                o[nj][0] = o[nj][1] = o[nj][2] = o[nj][3] = 0.f;
            }
            mA = mB = -INFINITY;  lA = lB = 0.f;
        }
    }

    // store [B,S,D] as bf16 hi/lo
    int ra = qt*64 + w*16 + (lane >> 2);
    #pragma unroll
    for (int nj = 0; nj < 8; nj++) {
        int d = nj*8 + (lane & 3)*2;
        #pragma unroll
        for (int half = 0; half < 2; half++) {
            int q = ra + half*8;
            float x = oT[nj][half*2], y = oT[nj][half*2+1];
            bf16 xh,xl,yh,yl;
            split1(x,xh,xl); split1(y,yh,yl);
            size_t idx = ((size_t)(b*SS + q))*DDIM + h*HDIM + d;
            *(u32*)&g_ahi[idx] = (u32)us(xh) | ((u32)us(yh) << 16);
            *(u32*)&g_alo[idx] = (u32)us(xl) | ((u32)us(yl) << 16);
        }
    }
}

// ---------------------------------------------------------------------------
// Output projection: d_out = att @ Wo, split MMA, fp32 output.
// ---------------------------------------------------------------------------
__global__ __launch_bounds__(256) void out_mma_kernel(float* __restrict__ out)
{
    __shared__ __align__(16) bf16 Ahi[128*40], Alo[128*40];
    __shared__ __align__(16) bf16 Bhi[32*136], Blo[32*136];

    const bf16* __restrict__ Whi = g_whi[3];
    const bf16* __restrict__ Wlo = g_wlo[3];
    const int m0 = blockIdx.y * 128;
    const int n0 = blockIdx.x * 128;
    const int t = threadIdx.x, lane = t & 31, w = t >> 5;
    const int wm = w & 3, wn = w >> 2;

    const int arow = t >> 1, acol = (t & 1) * 16;
    const int brow = t >> 3, bcol = (t & 7) * 16;

    float acc[2][8][4] = {};

    for (int k0 = 0; k0 < DDIM; k0 += 32) {
        uint4 a0h = *(const uint4*)&g_ahi[(size_t)(m0+arow)*DDIM + k0 + acol];
        uint4 a1h = *(const uint4*)&g_ahi[(size_t)(m0+arow)*DDIM + k0 + acol + 8];
        uint4 a0l = *(const uint4*)&g_alo[(size_t)(m0+arow)*DDIM + k0 + acol];
        uint4 a1l = *(const uint4*)&g_alo[(size_t)(m0+arow)*DDIM + k0 + acol + 8];
        uint4 b0h = *(const uint4*)&Whi[(k0+brow)*DDIM + n0 + bcol];
        uint4 b1h = *(const uint4*)&Whi[(k0+brow)*DDIM + n0 + bcol + 8];
        uint4 b0l = *(const uint4*)&Wlo[(k0+brow)*DDIM + n0 + bcol];
        uint4 b1l = *(const uint4*)&Wlo[(k0+brow)*DDIM + n0 + bcol + 8];
        __syncthreads();
        *(uint4*)&Ahi[arow*40 + acol]     = a0h;
        *(uint4*)&Ahi[arow*40 + acol + 8] = a1h;
        *(uint4*)&Alo[arow*40 + acol]     = a0l;
        *(uint4*)&Alo[arow*40 + acol + 8] = a1l;
        *(uint4*)&Bhi[brow*136 + bcol]     = b0h;
        *(uint4*)&Bhi[brow*136 + bcol + 8] = b1h;
        *(uint4*)&Blo[brow*136 + bcol]     = b0l;
        *(uint4*)&Blo[brow*136 + bcol + 8] = b1l;
        __syncthreads();

        #pragma unroll
        for (int kk = 0; kk < 2; kk++) {
            u32 afh[2][4], afl[2][4];
            #pragma unroll
            for (int mi = 0; mi < 2; mi++) {
                int r = wm*32 + mi*16 + (lane & 15);
                int c = kk*16 + ((lane >> 4) & 1) * 8;
                ldsm4(afh[mi][0],afh[mi][1],afh[mi][2],afh[mi][3], sptr(&Ahi[r*40 + c]));
                ldsm4(afl[mi][0],afl[mi][1],afl[mi][2],afl[mi][3], sptr(&Alo[r*40 + c]));
            }
            #pragma unroll
            for (int nj = 0; nj < 8; nj++) {
                u32 bh[2], bl[2];
                int r = kk*16 + (lane & 15);
                int c = wn*64 + nj*8;
                ldsm2t(bh[0], bh[1], sptr(&Bhi[r*136 + c]));
                ldsm2t(bl[0], bl[1], sptr(&Blo[r*136 + c]));
                #pragma unroll
                for (int mi = 0; mi < 2; mi++) {
                    mma16816(acc[mi][nj], afh[mi], bh);
                    mma16816(acc[mi][nj], afh[mi], bl);
                    mma16816(acc[mi][nj], afl[mi], bh);
                }
            }
        }
    }

    #pragma unroll
    for (int mi = 0; mi < 2; mi++) {
        int ra = m0 + wm*32 + mi*16 + (lane >> 2);
        #pragma unroll
        for (int nj = 0; nj < 8; nj++) {
            int col = n0 + wn*64 + nj*8 + (lane & 3)*2;
            *(float2*)&out[(size_t)ra*DDIM + col] =
                make_float2(acc[mi][nj][0], acc[mi][nj][1]);
            *(float2*)&out[(size_t)(ra+8)*DDIM + col] =
                make_float2(acc[mi][nj][2], acc[mi][nj][3]);
        }
    }
}

// ---------------------------------------------------------------------------
extern "C" void kernel_launch(void* const* d_in, const int* in_sizes, int n_in,
                              void* d_out, int out_size)
{
    const float* X     = (const float*)d_in[0];
    const float* freqs = (const float*)d_in[1];
    const float* Wq    = (const float*)d_in[2];
    const float* Wk    = (const float*)d_in[3];
    const float* Wv    = (const float*)d_in[4];
    const float* Wo    = (const float*)d_in[5];
    float* out = (float*)d_out;

    cudaFuncSetAttribute(attn_mma_kernel,
                         cudaFuncAttributeMaxDynamicSharedMemorySize, ASMEM);

    split_kernel<<<(MM*DDIM/4 + 255)/256, 256>>>(X,  0, MM*DDIM/4);
    split_kernel<<<(DDIM*DDIM/4 + 255)/256, 256>>>(Wq, 1, DDIM*DDIM/4);
    split_kernel<<<(DDIM*DDIM/4 + 255)/256, 256>>>(Wk, 2, DDIM*DDIM/4);
    split_kernel<<<(DDIM*DDIM/4 + 255)/256, 256>>>(Wv, 3, DDIM*DDIM/4);
    split_kernel<<<(DDIM*DDIM/4 + 255)/256, 256>>>(Wo, 4, DDIM*DDIM/4);

    qkv_mma_kernel<<<dim3(8, 32, 3), 256>>>(freqs);
    attn_mma_kernel<<<dim3(32, HH, BB), 128, ASMEM>>>();
    out_mma_kernel<<<dim3(8, 32, 1), 256>>>(out);
}

// round 6
// speedup vs baseline: 3.6035x; 1.1258x over previous
#include <cuda_runtime.h>
#include <cuda_bf16.h>
#include <math.h>

#define BB 2
#define SS 2048
#define DDIM 1024
#define HH 16
#define HDIM 64
#define MM (BB*SS)
#define NKT 32

typedef unsigned int u32;
typedef unsigned short u16;
typedef __nv_bfloat16 bf16;

// ---- scratch (allocation-free rule: __device__ globals) ----
__device__ __align__(16) bf16 g_xhi[MM*DDIM], g_xlo[MM*DDIM];
__device__ __align__(16) bf16 g_whi[4][DDIM*DDIM], g_wlo[4][DDIM*DDIM];   // Wq,Wk,Wv,Wo
__device__ __align__(16) bf16 g_qhi[MM*DDIM], g_qlo[MM*DDIM];             // [B,H,S,HD]
__device__ __align__(16) bf16 g_khi[MM*DDIM], g_klo[MM*DDIM];
__device__ __align__(16) bf16 g_vhi[MM*DDIM], g_vlo[MM*DDIM];
__device__ __align__(16) bf16 g_ahi[MM*DDIM], g_alo[MM*DDIM];             // attn out [B,S,D]

// ---- helpers ----
__device__ __forceinline__ u32 sptr(const void* p){ return (u32)__cvta_generic_to_shared(p); }

__device__ __forceinline__ void ldsm4(u32& r0,u32& r1,u32& r2,u32& r3,u32 a){
    asm volatile("ldmatrix.sync.aligned.m8n8.x4.shared.b16 {%0,%1,%2,%3}, [%4];"
                 : "=r"(r0),"=r"(r1),"=r"(r2),"=r"(r3) : "r"(a));
}
__device__ __forceinline__ void ldsm4t(u32& r0,u32& r1,u32& r2,u32& r3,u32 a){
    asm volatile("ldmatrix.sync.aligned.m8n8.x4.trans.shared.b16 {%0,%1,%2,%3}, [%4];"
                 : "=r"(r0),"=r"(r1),"=r"(r2),"=r"(r3) : "r"(a));
}
__device__ __forceinline__ void mma16816(float* c, const u32* a, const u32* b){
    asm volatile("mma.sync.aligned.m16n8k16.row.col.f32.bf16.bf16.f32 "
                 "{%0,%1,%2,%3},{%4,%5,%6,%7},{%8,%9},{%0,%1,%2,%3};"
                 : "+f"(c[0]),"+f"(c[1]),"+f"(c[2]),"+f"(c[3])
                 : "r"(a[0]),"r"(a[1]),"r"(a[2]),"r"(a[3]),"r"(b[0]),"r"(b[1]));
}
__device__ __forceinline__ void cpa(void* dst, const void* src){
    asm volatile("cp.async.cg.shared.global [%0], [%1], 16;"
                 :: "r"(sptr(dst)), "l"(src));
}
#define CP_COMMIT() asm volatile("cp.async.commit_group;")
#define CP_WAIT0()  asm volatile("cp.async.wait_group 0;")

__device__ __forceinline__ u16 us(bf16 x){ return __bfloat16_as_ushort(x); }
__device__ __forceinline__ void split1(float x, bf16& h, bf16& l){
    h = __float2bfloat16(x);
    l = __float2bfloat16(x - __bfloat162float(h));
}

// ---------------------------------------------------------------------------
// Merged prep: split X + all 4 weights into bf16 hi/lo in one launch.
// ---------------------------------------------------------------------------
#define NX_CHUNK (MM*DDIM/4)
#define NW_CHUNK (DDIM*DDIM/4)

__global__ __launch_bounds__(256) void split_all_kernel(
    const float* __restrict__ X, const float* __restrict__ Wq,
    const float* __restrict__ Wk, const float* __restrict__ Wv,
    const float* __restrict__ Wo)
{
    int i = blockIdx.x * 256 + threadIdx.x;
    const float* src; bf16 *hi, *lo; int off;
    if (i < NX_CHUNK) { src = X; hi = g_xhi; lo = g_xlo; off = i; }
    else {
        int j = i - NX_CHUNK;
        int wsel = j / NW_CHUNK; off = j - wsel * NW_CHUNK;
        src = (wsel==0)?Wq:(wsel==1)?Wk:(wsel==2)?Wv:Wo;
        hi = g_whi[wsel]; lo = g_wlo[wsel];
    }
    float4 v = ((const float4*)src)[off];
    bf16 h0,l0,h1,l1,h2,l2,h3,l3;
    split1(v.x,h0,l0); split1(v.y,h1,l1); split1(v.z,h2,l2); split1(v.w,h3,l3);
    uint2 hw, lw;
    hw.x = (u32)us(h0) | ((u32)us(h1) << 16);
    hw.y = (u32)us(h2) | ((u32)us(h3) << 16);
    lw.x = (u32)us(l0) | ((u32)us(l1) << 16);
    lw.y = (u32)us(l2) | ((u32)us(l3) << 16);
    *(uint2*)&hi[off*4] = hw;
    *(uint2*)&lo[off*4] = lw;
}

// ---------------------------------------------------------------------------
// Projection GEMM core: C = A @ W (hi/lo split, 3 MMAs), double-buffered
// cp.async, ldsm4 B loads. Tile 128x128, k-step 32, 256 thr (8 warps 4m x 2n).
// Shared layout per buffer (elems): Ah[128*40] Al[128*40] Bh[32*136] Bl[32*136]
// ---------------------------------------------------------------------------
#define PROJ_BUF_ELEMS (2*128*40 + 2*32*136)
#define PROJ_SMEM (2 * PROJ_BUF_ELEMS * 2)

__device__ __forceinline__ void proj_load_step(
    bf16* buf, const bf16* Ahi_g, const bf16* Alo_g,
    const bf16* Whi_g, const bf16* Wlo_g,
    int m0, int n0, int k0, int t)
{
    bf16* Ah = buf;
    bf16* Al = buf + 128*40;
    bf16* Bh = buf + 2*128*40;
    bf16* Bl = buf + 2*128*40 + 32*136;
    #pragma unroll
    for (int i = 0; i < 2; i++) {
        int c = t + i*256;
        int ar = c >> 2, ac = (c & 3) * 8;
        cpa(&Ah[ar*40 + ac], &Ahi_g[(size_t)(m0+ar)*DDIM + k0 + ac]);
        cpa(&Al[ar*40 + ac], &Alo_g[(size_t)(m0+ar)*DDIM + k0 + ac]);
        int br = c >> 4, bc = (c & 15) * 8;
        cpa(&Bh[br*136 + bc], &Whi_g[(size_t)(k0+br)*DDIM + n0 + bc]);
        cpa(&Bl[br*136 + bc], &Wlo_g[(size_t)(k0+br)*DDIM + n0 + bc]);
    }
}

__device__ __forceinline__ void proj_gemm(
    float acc[2][8][4], bf16* smem,
    const bf16* Ahi_g, const bf16* Alo_g,
    const bf16* Whi_g, const bf16* Wlo_g,
    int m0, int n0, int t)
{
    const int lane = t & 31, w = t >> 5;
    const int wm = w & 3, wn = w >> 2;

    proj_load_step(smem, Ahi_g, Alo_g, Whi_g, Wlo_g, m0, n0, 0, t);
    CP_COMMIT();

    for (int k0 = 0; k0 < DDIM; k0 += 32) {
        CP_WAIT0();
        __syncthreads();
        int buf = (k0 >> 5) & 1;
        if (k0 + 32 < DDIM) {
            proj_load_step(smem + (buf^1)*PROJ_BUF_ELEMS,
                           Ahi_g, Alo_g, Whi_g, Wlo_g, m0, n0, k0 + 32, t);
            CP_COMMIT();
        }
        bf16* Ah = smem + buf*PROJ_BUF_ELEMS;
        bf16* Al = Ah + 128*40;
        bf16* Bh = Al + 128*40;
        bf16* Bl = Bh + 32*136;

        #pragma unroll
        for (int kk = 0; kk < 2; kk++) {
            u32 afh[2][4], afl[2][4];
            #pragma unroll
            for (int mi = 0; mi < 2; mi++) {
                int r = wm*32 + mi*16 + (lane & 15);
                int c = kk*16 + ((lane >> 4) & 1) * 8;
                ldsm4(afh[mi][0],afh[mi][1],afh[mi][2],afh[mi][3], sptr(&Ah[r*40 + c]));
                ldsm4(afl[mi][0],afl[mi][1],afl[mi][2],afl[mi][3], sptr(&Al[r*40 + c]));
            }
            #pragma unroll
            for (int njp = 0; njp < 4; njp++) {
                u32 bh4[4], bl4[4];
                int r = kk*16 + (lane & 7) + ((lane >> 3) & 1) * 8;
                int c = wn*64 + njp*16 + ((lane >> 4) & 1) * 8;
                ldsm4t(bh4[0],bh4[1],bh4[2],bh4[3], sptr(&Bh[r*136 + c]));
                ldsm4t(bl4[0],bl4[1],bl4[2],bl4[3], sptr(&Bl[r*136 + c]));
                #pragma unroll
                for (int mi = 0; mi < 2; mi++) {
                    mma16816(acc[mi][njp*2],   afh[mi], bh4+0);
                    mma16816(acc[mi][njp*2],   afh[mi], bl4+0);
                    mma16816(acc[mi][njp*2],   afl[mi], bh4+0);
                    mma16816(acc[mi][njp*2+1], afh[mi], bh4+2);
                    mma16816(acc[mi][njp*2+1], afh[mi], bl4+2);
                    mma16816(acc[mi][njp*2+1], afl[mi], bh4+2);
                }
            }
        }
        __syncthreads();
    }
}

// ---------------------------------------------------------------------------
// QKV projection + rope epilogue, output bf16 hi/lo [B,H,S,HD].
// ---------------------------------------------------------------------------
__global__ __launch_bounds__(256) void qkv_mma_kernel(const float* __restrict__ freqs)
{
    extern __shared__ __align__(16) bf16 psm[];
    const int mode = blockIdx.z;
    const int m0 = blockIdx.y * 128, n0 = blockIdx.x * 128;
    const int t = threadIdx.x, lane = t & 31, w = t >> 5;
    const int wm = w & 3, wn = w >> 2;

    float acc[2][8][4] = {};
    proj_gemm(acc, psm, g_xhi, g_xlo, g_whi[mode], g_wlo[mode], m0, n0, t);

    bf16* __restrict__ dh = (mode == 0) ? g_qhi : (mode == 1) ? g_khi : g_vhi;
    bf16* __restrict__ dl = (mode == 0) ? g_qlo : (mode == 1) ? g_klo : g_vlo;
    #pragma unroll
    for (int mi = 0; mi < 2; mi++) {
        int ra = m0 + wm*32 + mi*16 + (lane >> 2);
        #pragma unroll
        for (int nj = 0; nj < 8; nj++) {
            int col = n0 + wn*64 + nj*8 + (lane & 3)*2;
            int hh = col >> 6, dd = col & 63;
            #pragma unroll
            for (int half = 0; half < 2; half++) {
                int r = ra + half*8;
                int b = r >> 11, s = r & 2047;
                float x = acc[mi][nj][half*2], y = acc[mi][nj][half*2+1];
                if (mode < 2) {
                    float cs = freqs[s*HDIM + dd], sn = freqs[s*HDIM + dd + 1];
                    float nx = x*cs - y*sn;
                    float ny = x*sn + y*cs;
                    x = nx; y = ny;
                }
                bf16 xh,xl,yh,yl;
                split1(x,xh,xl); split1(y,yh,yl);
                size_t idx = ((size_t)(b*HH + hh)*SS + s)*HDIM + dd;
                *(u32*)&dh[idx] = (u32)us(xh) | ((u32)us(yh) << 16);
                *(u32*)&dl[idx] = (u32)us(xl) | ((u32)us(yl) << 16);
            }
        }
    }
}

// ---------------------------------------------------------------------------
// Output projection: d_out = att @ Wo, fp32 output.
// ---------------------------------------------------------------------------
__global__ __launch_bounds__(256) void out_mma_kernel(float* __restrict__ out)
{
    extern __shared__ __align__(16) bf16 psm[];
    const int m0 = blockIdx.y * 128, n0 = blockIdx.x * 128;
    const int t = threadIdx.x, lane = t & 31, w = t >> 5;
    const int wm = w & 3, wn = w >> 2;

    float acc[2][8][4] = {};
    proj_gemm(acc, psm, g_ahi, g_alo, g_whi[3], g_wlo[3], m0, n0, t);

    #pragma unroll
    for (int mi = 0; mi < 2; mi++) {
        int ra = m0 + wm*32 + mi*16 + (lane >> 2);
        #pragma unroll
        for (int nj = 0; nj < 8; nj++) {
            int col = n0 + wn*64 + nj*8 + (lane & 3)*2;
            *(float2*)&out[(size_t)ra*DDIM + col] =
                make_float2(acc[mi][nj][0], acc[mi][nj][1]);
            *(float2*)&out[(size_t)(ra+8)*DDIM + col] =
                make_float2(acc[mi][nj][2], acc[mi][nj][3]);
        }
    }
}

// ---------------------------------------------------------------------------
// Attention: 256 thr (8 warps, each m16), q-tile 128, K/V tiles 64x64
// double-buffered via cp.async. 3-MMA hi/lo split both GEMMs. Per-1024-key
// chunk softmax normalization + reset (replicates reference chunking).
// Shared: Qh[128*72] Ql[128*72] KV[2][4][64*72] (Kh,Kl,Vh,Vl)
// ---------------------------------------------------------------------------
#define KVT (64*72)
#define ASMEM ((2*128*72 + 8*KVT) * 2)

__device__ __forceinline__ void attn_load_kv(
    bf16* kvbuf, const bf16* Kgh, const bf16* Kgl,
    const bf16* Vgh, const bf16* Vgl, int kt, int t)
{
    #pragma unroll
    for (int i = 0; i < 2; i++) {
        int c = t + i*256;
        int row = c >> 3, cc = (c & 7) * 8;
        size_t g = (size_t)(kt*64 + row)*64 + cc;
        int s = row*72 + cc;
        cpa(&kvbuf[s],         &Kgh[g]);
        cpa(&kvbuf[s + KVT],   &Kgl[g]);
        cpa(&kvbuf[s + 2*KVT], &Vgh[g]);
        cpa(&kvbuf[s + 3*KVT], &Vgl[g]);
    }
}

__global__ __launch_bounds__(256) void attn_mma_kernel()
{
    extern __shared__ __align__(16) bf16 sm[];
    bf16* Qh = sm;
    bf16* Ql = sm + 128*72;
    bf16* KV = sm + 2*128*72;

    const int qt = blockIdx.x, h = blockIdx.y, b = blockIdx.z;
    const int t = threadIdx.x, lane = t & 31, w = t >> 5;

    const size_t base = ((size_t)(b*HH + h))*SS*HDIM;
    const bf16* __restrict__ Qgh = g_qhi + base + (size_t)qt*128*HDIM;
    const bf16* __restrict__ Qgl = g_qlo + base + (size_t)qt*128*HDIM;
    const bf16* __restrict__ Kgh = g_khi + base;
    const bf16* __restrict__ Kgl = g_klo + base;
    const bf16* __restrict__ Vgh = g_vhi + base;
    const bf16* __restrict__ Vgl = g_vlo + base;

    // Q tile (128x64) hi/lo — plain vector loads
    #pragma unroll
    for (int i = 0; i < 4; i++) {
        int c = t + i*256;
        int row = c >> 3, cc = (c & 7) * 8;
        *(uint4*)&Qh[row*72 + cc] = *(const uint4*)&Qgh[(size_t)row*64 + cc];
        *(uint4*)&Ql[row*72 + cc] = *(const uint4*)&Qgl[(size_t)row*64 + cc];
    }
    // prefetch KV tile 0
    attn_load_kv(KV, Kgh, Kgl, Vgh, Vgl, 0, t);
    CP_COMMIT();
    __syncthreads();

    // resident Q fragments
    u32 qfh[4][4], qfl[4][4];
    #pragma unroll
    for (int g = 0; g < 4; g++) {
        int r = w*16 + (lane & 15);
        int c = g*16 + ((lane >> 4) & 1) * 8;
        ldsm4(qfh[g][0],qfh[g][1],qfh[g][2],qfh[g][3], sptr(&Qh[r*72 + c]));
        ldsm4(qfl[g][0],qfl[g][1],qfl[g][2],qfl[g][3], sptr(&Ql[r*72 + c]));
    }

    float o[8][4] = {}, oT[8][4] = {};
    float mA = -INFINITY, lA = 0.f, mB = -INFINITY, lB = 0.f;

    for (int kt = 0; kt < NKT; kt++) {
        CP_WAIT0();
        __syncthreads();
        if (kt + 1 < NKT) {
            attn_load_kv(KV + ((kt+1)&1)*4*KVT, Kgh, Kgl, Vgh, Vgl, kt+1, t);
            CP_COMMIT();
        }
        bf16* Kh = KV + (kt&1)*4*KVT;
        bf16* Kl = Kh + KVT;
        bf16* Vh = Kh + 2*KVT;
        bf16* Vl = Kh + 3*KVT;

        // S = Q K^T : m16 x n64 x k64
        float s[8][4] = {};
        #pragma unroll
        for (int g = 0; g < 4; g++) {
            #pragma unroll
            for (int njp = 0; njp < 4; njp++) {
                u32 bh4[4], bl4[4];
                int r = njp*16 + (lane & 7) + ((lane >> 4) & 1) * 8;
                int c = g*16 + ((lane >> 3) & 1) * 8;
                ldsm4(bh4[0],bh4[1],bh4[2],bh4[3], sptr(&Kh[r*72 + c]));
                ldsm4(bl4[0],bl4[1],bl4[2],bl4[3], sptr(&Kl[r*72 + c]));
                mma16816(s[njp*2],   qfh[g], bh4+0);
                mma16816(s[njp*2],   qfh[g], bl4+0);
                mma16816(s[njp*2],   qfl[g], bh4+0);
                mma16816(s[njp*2+1], qfh[g], bh4+2);
                mma16816(s[njp*2+1], qfh[g], bl4+2);
                mma16816(s[njp*2+1], qfl[g], bh4+2);
            }
        }

        // online softmax (rows rA = lane>>2, rB = +8), quad reduce
        float mtA = -INFINITY, mtB = -INFINITY;
        #pragma unroll
        for (int nj = 0; nj < 8; nj++) {
            #pragma unroll
            for (int q4 = 0; q4 < 4; q4++) s[nj][q4] *= 0.125f;
            mtA = fmaxf(mtA, fmaxf(s[nj][0], s[nj][1]));
            mtB = fmaxf(mtB, fmaxf(s[nj][2], s[nj][3]));
        }
        #pragma unroll
        for (int ofs = 1; ofs <= 2; ofs <<= 1) {
            mtA = fmaxf(mtA, __shfl_xor_sync(0xffffffffu, mtA, ofs));
            mtB = fmaxf(mtB, __shfl_xor_sync(0xffffffffu, mtB, ofs));
        }
        float mnA = fmaxf(mA, mtA), mnB = fmaxf(mB, mtB);
        float alA = __expf(mA - mnA), alB = __expf(mB - mnB);
        float rsA = 0.f, rsB = 0.f;
        #pragma unroll
        for (int nj = 0; nj < 8; nj++) {
            s[nj][0] = __expf(s[nj][0] - mnA);
            s[nj][1] = __expf(s[nj][1] - mnA);
            s[nj][2] = __expf(s[nj][2] - mnB);
            s[nj][3] = __expf(s[nj][3] - mnB);
            rsA += s[nj][0] + s[nj][1];
            rsB += s[nj][2] + s[nj][3];
        }
        #pragma unroll
        for (int ofs = 1; ofs <= 2; ofs <<= 1) {
            rsA += __shfl_xor_sync(0xffffffffu, rsA, ofs);
            rsB += __shfl_xor_sync(0xffffffffu, rsB, ofs);
        }
        lA = lA * alA + rsA;  mA = mnA;
        lB = lB * alB + rsB;  mB = mnB;
        #pragma unroll
        for (int nj = 0; nj < 8; nj++) {
            o[nj][0] *= alA; o[nj][1] *= alA;
            o[nj][2] *= alB; o[nj][3] *= alB;
        }

        // repack P (C-frag) -> A-frag, hi/lo split, registers only
        u32 pfh[4][4], pfl[4][4];
        #pragma unroll
        for (int g = 0; g < 4; g++) {
            #pragma unroll
            for (int q4 = 0; q4 < 4; q4++) {
                int tile = 2*g + (q4 >> 1);
                float p0 = s[tile][(q4 & 1)*2], p1 = s[tile][(q4 & 1)*2 + 1];
                bf16 h0,l0,h1,l1;
                split1(p0,h0,l0); split1(p1,h1,l1);
                pfh[g][q4] = (u32)us(h0) | ((u32)us(h1) << 16);
                pfl[g][q4] = (u32)us(l0) | ((u32)us(l1) << 16);
            }
        }

        // O += P V : m16 x n64 x k64
        #pragma unroll
        for (int g = 0; g < 4; g++) {
            #pragma unroll
            for (int njp = 0; njp < 4; njp++) {
                u32 vh4[4], vl4[4];
                int r = g*16 + (lane & 7) + ((lane >> 3) & 1) * 8;
                int c = njp*16 + ((lane >> 4) & 1) * 8;
                ldsm4t(vh4[0],vh4[1],vh4[2],vh4[3], sptr(&Vh[r*72 + c]));
                ldsm4t(vl4[0],vl4[1],vl4[2],vl4[3], sptr(&Vl[r*72 + c]));
                mma16816(o[njp*2],   pfh[g], vh4+0);
                mma16816(o[njp*2],   pfh[g], vl4+0);
                mma16816(o[njp*2],   pfl[g], vh4+0);
                mma16816(o[njp*2+1], pfh[g], vh4+2);
                mma16816(o[njp*2+1], pfh[g], vl4+2);
                mma16816(o[njp*2+1], pfl[g], vh4+2);
            }
        }

        // chunk boundary (1024 keys = 16 tiles): normalize, accumulate, reset
        if ((kt & 15) == 15) {
            float iA = 1.f / lA, iB = 1.f / lB;
            #pragma unroll
            for (int nj = 0; nj < 8; nj++) {
                oT[nj][0] += o[nj][0] * iA;  oT[nj][1] += o[nj][1] * iA;
                oT[nj][2] += o[nj][2] * iB;  oT[nj][3] += o[nj][3] * iB;
                o[nj][0] = o[nj][1] = o[nj][2] = o[nj][3] = 0.f;
            }
            mA = mB = -INFINITY;  lA = lB = 0.f;
        }
        __syncthreads();
    }

    // store [B,S,D] as bf16 hi/lo
    int ra = qt*128 + w*16 + (lane >> 2);
    #pragma unroll
    for (int nj = 0; nj < 8; nj++) {
        int d = nj*8 + (lane & 3)*2;
        #pragma unroll
        for (int half = 0; half < 2; half++) {
            int q = ra + half*8;
            float x = oT[nj][half*2], y = oT[nj][half*2+1];
            bf16 xh,xl,yh,yl;
            split1(x,xh,xl); split1(y,yh,yl);
            size_t idx = ((size_t)(b*SS + q))*DDIM + h*HDIM + d;
            *(u32*)&g_ahi[idx] = (u32)us(xh) | ((u32)us(yh) << 16);
            *(u32*)&g_alo[idx] = (u32)us(xl) | ((u32)us(yl) << 16);
        }
    }
}

// ---------------------------------------------------------------------------
extern "C" void kernel_launch(void* const* d_in, const int* in_sizes, int n_in,
                              void* d_out, int out_size)
{
    const float* X     = (const float*)d_in[0];
    const float* freqs = (const float*)d_in[1];
    const float* Wq    = (const float*)d_in[2];
    const float* Wk    = (const float*)d_in[3];
    const float* Wv    = (const float*)d_in[4];
    const float* Wo    = (const float*)d_in[5];
    float* out = (float*)d_out;

    cudaFuncSetAttribute(attn_mma_kernel,
                         cudaFuncAttributeMaxDynamicSharedMemorySize, ASMEM);
    cudaFuncSetAttribute(qkv_mma_kernel,
                         cudaFuncAttributeMaxDynamicSharedMemorySize, PROJ_SMEM);
    cudaFuncSetAttribute(out_mma_kernel,
                         cudaFuncAttributeMaxDynamicSharedMemorySize, PROJ_SMEM);

    int total_chunks = NX_CHUNK + 4*NW_CHUNK;
    split_all_kernel<<<(total_chunks + 255)/256, 256>>>(X, Wq, Wk, Wv, Wo);
    qkv_mma_kernel<<<dim3(8, 32, 3), 256, PROJ_SMEM>>>(freqs);
    attn_mma_kernel<<<dim3(16, HH, BB), 256, ASMEM>>>();
    out_mma_kernel<<<dim3(8, 32, 1), 256, PROJ_SMEM>>>(out);
}